// round 6
// baseline (speedup 1.0000x reference)
#include <cuda_runtime.h>
#include <cuda_bf16.h>
#include <cstdint>

#define NODES 40000
#define EDGES 640000
#define DIN   128
#define HC    128
#define OC    64

typedef unsigned long long ull;

// single dynamic-shared declaration for the whole TU
extern __shared__ char dynsm[];

// ---------------- device scratch ------------------------------------------
__device__ float g_xm[(size_t)NODES * HC];
__device__ float g_xs[(size_t)NODES * OC];
__device__ float g_denom[(size_t)NODES * 2];
__device__ float g_agg[(size_t)NODES * HC];
__device__ float g_le_fallback[(size_t)EDGES * HC];
// W_edge^T split into bf16 hi/lo: [n][k] row-major, padded row stride 68 words
// (136 bf16 = 272B). size = 128 * 68 * 4 = 34816 B each.
__device__ __align__(16) uint32_t g_Bhi[128 * 68];
__device__ __align__(16) uint32_t g_Blo[128 * 68];

// ---------------- helpers ----------------------------------------------------
__device__ __forceinline__ void red_add_v4(float* p, float a, float b, float c, float d) {
    asm volatile("red.global.add.v4.f32 [%0], {%1,%2,%3,%4};"
                 :: "l"(p), "f"(a), "f"(b), "f"(c), "f"(d) : "memory");
}
__device__ __forceinline__ void red_add_f32(float* p, float v) {
    asm volatile("red.global.add.f32 [%0], %1;" :: "l"(p), "f"(v) : "memory");
}
// m16n8k16 row.col bf16 MMA, f32 accumulate (base-target HMMA, works on compute_103)
__device__ __forceinline__ void mma_bf16(float* c, const uint32_t* a, const uint32_t* b) {
    asm volatile("mma.sync.aligned.m16n8k16.row.col.f32.bf16.bf16.f32 "
                 "{%0,%1,%2,%3}, {%4,%5,%6,%7}, {%8,%9}, {%0,%1,%2,%3};"
                 : "+f"(c[0]), "+f"(c[1]), "+f"(c[2]), "+f"(c[3])
                 : "r"(a[0]), "r"(a[1]), "r"(a[2]), "r"(a[3]), "r"(b[0]), "r"(b[1]));
}
__device__ __forceinline__ uint32_t pack_bf16x2_split(float v0, float v1, uint32_t& lo) {
    __nv_bfloat16 h0 = __float2bfloat16_rn(v0);
    __nv_bfloat16 h1 = __float2bfloat16_rn(v1);
    __nv_bfloat16 l0 = __float2bfloat16_rn(v0 - __bfloat162float(h0));
    __nv_bfloat16 l1 = __float2bfloat16_rn(v1 - __bfloat162float(h1));
    lo = (uint32_t)__bfloat16_as_ushort(l0) | ((uint32_t)__bfloat16_as_ushort(l1) << 16);
    return (uint32_t)__bfloat16_as_ushort(h0) | ((uint32_t)__bfloat16_as_ushort(h1) << 16);
}

// ---------------- K0: init --------------------------------------------------
__global__ void init_kernel() {
    int i = blockIdx.x * blockDim.x + threadIdx.x;
    if (i < NODES * HC) g_agg[i] = 0.0f;
    if (i < NODES * 2)  g_denom[i] = 0.0f;
}

// ---------------- prep: W_edge^T -> bf16 hi/lo padded [n][k] images ----------
__global__ void prep_kernel(const float* __restrict__ W_edge) {
    int p = blockIdx.x * 256 + threadIdx.x;   // 8192 = 128 n x 64 k-pairs
    if (p >= 8192) return;
    int n  = p >> 6;
    int kp = p & 63;
    int k  = kp * 2;
    uint32_t lo;
    uint32_t hi = pack_bf16x2_split(W_edge[k * HC + n], W_edge[(k + 1) * HC + n], lo);
    g_Bhi[n * 68 + kp] = hi;
    g_Blo[n * 68 + kp] = lo;
}

// ---------------- K1: node GEMMs (known-good) --------------------------------
__global__ void node_kernel(const float* __restrict__ x,
                            const float* __restrict__ W_msg,
                            const float* __restrict__ b_msg,
                            const float* __restrict__ W_self,
                            const float* __restrict__ b_self) {
    float* smf = (float*)dynsm;
    float* Xs = smf;
    float* Wm = smf + 64 * 128;
    float* Wf = Wm + 128 * 128;
    int tid = threadIdx.x;

    const float4* xg = (const float4*)(x + (size_t)blockIdx.x * 64 * DIN);
#pragma unroll
    for (int i = 0; i < 8; i++)  ((float4*)Xs)[tid + i * 256] = xg[tid + i * 256];
#pragma unroll
    for (int i = 0; i < 16; i++) ((float4*)Wm)[tid + i * 256] = ((const float4*)W_msg)[tid + i * 256];
#pragma unroll
    for (int i = 0; i < 8; i++)  ((float4*)Wf)[tid + i * 256] = ((const float4*)W_self)[tid + i * 256];
    __syncthreads();

    int lane = tid & 31, ty = tid >> 5;
    int lane4 = lane * 4;
    const float* Xr = Xs + ty * 8 * DIN;
    {
        float acc[8][4];
#pragma unroll
        for (int r = 0; r < 8; r++) { acc[r][0] = acc[r][1] = acc[r][2] = acc[r][3] = 0.f; }
#pragma unroll 4
        for (int k = 0; k < 128; k++) {
            float4 bq = *(float4*)(Wm + k * 128 + lane4);
#pragma unroll
            for (int r = 0; r < 8; r++) {
                float av = Xr[r * DIN + k];
                acc[r][0] += av * bq.x; acc[r][1] += av * bq.y;
                acc[r][2] += av * bq.z; acc[r][3] += av * bq.w;
            }
        }
        float4 bm = *(const float4*)(b_msg + lane4);
#pragma unroll
        for (int r = 0; r < 8; r++) {
            int n = blockIdx.x * 64 + ty * 8 + r;
            float4 v; v.x = acc[r][0] + bm.x; v.y = acc[r][1] + bm.y;
            v.z = acc[r][2] + bm.z; v.w = acc[r][3] + bm.w;
            *(float4*)(g_xm + (size_t)n * HC + lane4) = v;
        }
    }
    {
        int lane2 = lane * 2;
        float acc[8][2];
#pragma unroll
        for (int r = 0; r < 8; r++) { acc[r][0] = acc[r][1] = 0.f; }
#pragma unroll 4
        for (int k = 0; k < 128; k++) {
            float2 bq = *(float2*)(Wf + k * 64 + lane2);
#pragma unroll
            for (int r = 0; r < 8; r++) {
                float av = Xr[r * DIN + k];
                acc[r][0] += av * bq.x; acc[r][1] += av * bq.y;
            }
        }
        float2 bs = *(const float2*)(b_self + lane2);
#pragma unroll
        for (int r = 0; r < 8; r++) {
            int n = blockIdx.x * 64 + ty * 8 + r;
            float2 v; v.x = acc[r][0] + bs.x; v.y = acc[r][1] + bs.y;
            *(float2*)(g_xs + (size_t)n * OC + lane2) = v;
        }
    }
}

// ---------------- K2: HMMA edge GEMM + fused attention scatter ---------------
// Tile = 128 edges x 128 cols, K = 128. bf16 3-term split on mma.sync m16n8k16.
// 8 warps: warp w -> rows [ (w>>1)*32, +32 ), cols [ (w&1)*64, +64 ).
// smem (bytes):
//   16     : b_edge bias (512B)
//   1024   : A_hi  (34816 = 128 rows x 68 words)
//   35840  : A_lo  (34816)
//   70656  : B_hi  (34816)
//   105472 : B_lo  (34816)  -> total 140288
//   le_stage aliases 1024.. (128 rows x 132 words = 67584B <= 69632) after MMA
#define SM_AHI   1024
#define SM_ALO   35840
#define SM_BHI   70656
#define SM_BLO   105472
#define SM_TOTAL 140288
#define LE_STRIDE 132

__global__ void __launch_bounds__(256, 1) edge_kernel(
        const float* __restrict__ edge_attr,
        const float* __restrict__ b_edge,
        const float* __restrict__ att,
        const int*   __restrict__ srcIdx,
        const int*   __restrict__ dstIdx,
        float* __restrict__ le_out) {
    char* sm = dynsm;
    int tid = threadIdx.x;
    int wid = tid >> 5;
    int lane = tid & 31;
    float* b_s = (float*)(sm + 16);
    float* le_stage = (float*)(sm + SM_AHI);
    uint32_t* Ah32 = (uint32_t*)(sm + SM_AHI);
    uint32_t* Al32 = (uint32_t*)(sm + SM_ALO);
    uint32_t* Bh32 = (uint32_t*)(sm + SM_BHI);
    uint32_t* Bl32 = (uint32_t*)(sm + SM_BLO);

    if (tid < 128) b_s[tid] = b_edge[tid];

    // B images from gmem (L2-hot): 2176 uint4 each
    {
        const uint4* bh = (const uint4*)g_Bhi;
        const uint4* bl = (const uint4*)g_Blo;
        uint4* dh = (uint4*)Bh32;
        uint4* dl = (uint4*)Bl32;
#pragma unroll
        for (int i = 0; i < 9; i++) {
            int idx = tid + i * 256;
            if (idx < 2176) { dh[idx] = bh[idx]; dl[idx] = bl[idx]; }
        }
    }

    // A tile: 128 edges x 128 f32 -> split bf16 hi/lo, padded stride 68 words
    {
        const float2* src = (const float2*)(edge_attr + (size_t)blockIdx.x * 128 * DIN);
#pragma unroll
        for (int i = 0; i < 32; i++) {
            int p = tid + i * 256;            // pair index 0..8191
            int row = p >> 6;
            int kp  = p & 63;
            float2 v = src[p];
            uint32_t lo;
            uint32_t hi = pack_bf16x2_split(v.x, v.y, lo);
            Ah32[row * 68 + kp] = hi;
            Al32[row * 68 + kp] = lo;
        }
    }
    __syncthreads();

    // ---- MMA mainloop ----
    int rowg = wid >> 1;          // 0..3  -> rows rowg*32..+32
    int colg = wid & 1;           // 0..1  -> cols colg*64..+64
    int r   = lane >> 2;          // 0..7
    int tig = lane & 3;           // 0..3

    float acc[2][8][4];
#pragma unroll
    for (int mt = 0; mt < 2; mt++)
#pragma unroll
        for (int nf = 0; nf < 8; nf++)
#pragma unroll
            for (int q = 0; q < 4; q++) acc[mt][nf][q] = 0.f;

#pragma unroll
    for (int ks = 0; ks < 8; ks++) {
        int kw = ks * 8 + tig;
        uint32_t ah[2][4], al[2][4];
#pragma unroll
        for (int mt = 0; mt < 2; mt++) {
            int base = (rowg * 32 + mt * 16 + r) * 68 + kw;
            ah[mt][0] = Ah32[base];            ah[mt][1] = Ah32[base + 8 * 68];
            ah[mt][2] = Ah32[base + 4];        ah[mt][3] = Ah32[base + 8 * 68 + 4];
            al[mt][0] = Al32[base];            al[mt][1] = Al32[base + 8 * 68];
            al[mt][2] = Al32[base + 4];        al[mt][3] = Al32[base + 8 * 68 + 4];
        }
#pragma unroll
        for (int nf = 0; nf < 8; nf++) {
            int nb = (colg * 64 + nf * 8 + r) * 68 + kw;
            uint32_t bh[2] = { Bh32[nb], Bh32[nb + 4] };
            uint32_t bl[2] = { Bl32[nb], Bl32[nb + 4] };
            mma_bf16(acc[0][nf], ah[0], bh);
            mma_bf16(acc[1][nf], ah[1], bh);
            mma_bf16(acc[0][nf], ah[0], bl);
            mma_bf16(acc[1][nf], ah[1], bl);
            mma_bf16(acc[0][nf], al[0], bh);
            mma_bf16(acc[1][nf], al[1], bh);
        }
    }
    __syncthreads();   // all smem A/B reads complete before le_stage overwrite

    // ---- epilogue: bias add -> le_stage (aliases A region) ----
#pragma unroll
    for (int mt = 0; mt < 2; mt++) {
#pragma unroll
        for (int nf = 0; nf < 8; nf++) {
            int row = rowg * 32 + mt * 16 + r;
            int col = colg * 64 + nf * 8 + tig * 2;
            float bb0 = b_s[col], bb1 = b_s[col + 1];
            float2 v0; v0.x = acc[mt][nf][0] + bb0; v0.y = acc[mt][nf][1] + bb1;
            float2 v1; v1.x = acc[mt][nf][2] + bb0; v1.y = acc[mt][nf][3] + bb1;
            *(float2*)(le_stage + (size_t)row * LE_STRIDE + col) = v0;
            *(float2*)(le_stage + (size_t)(row + 8) * LE_STRIDE + col) = v1;
        }
    }
    __syncthreads();

    // ---- pass A: coalesced le store to gmem ----
    {
        float* lo = le_out + (size_t)blockIdx.x * 128 * HC;
#pragma unroll
        for (int i = 0; i < 64; i++) {
            int idx = tid + i * 256;           // 0..16383
            int row = idx >> 7, col = idx & 127;
            lo[idx] = le_stage[(size_t)row * LE_STRIDE + col];
        }
    }

    // ---- pass B: attention + exp + scatter. 8 warps x 16 edges ----
    {
        int lane4 = lane * 4;
        float4 attv = *(const float4*)(att + lane4);
        int head = lane >> 4;
#pragma unroll
        for (int j = 0; j < 16; j++) {
            int el = wid * 16 + j;
            int e = blockIdx.x * 128 + el;
            int s = srcIdx[e];
            int d = dstIdx[e];
            float4 lv = *(float4*)(le_stage + (size_t)el * LE_STRIDE + lane4);
            float4 xv = *(const float4*)(g_xm + (size_t)s * HC + lane4);
            float m0 = lv.x + xv.x, m1 = lv.y + xv.y, m2 = lv.z + xv.z, m3 = lv.w + xv.w;
            float p = m0 * attv.x + m1 * attv.y + m2 * attv.z + m3 * attv.w;
            p += __shfl_xor_sync(0xffffffffu, p, 1);
            p += __shfl_xor_sync(0xffffffffu, p, 2);
            p += __shfl_xor_sync(0xffffffffu, p, 4);
            p += __shfl_xor_sync(0xffffffffu, p, 8);
            float lr = p > 0.0f ? p : 0.2f * p;
            float ex = __expf(lr);
            red_add_v4(g_agg + (size_t)d * HC + lane4, m0 * ex, m1 * ex, m2 * ex, m3 * ex);
            if ((lane & 15) == 0) red_add_f32(&g_denom[d * 2 + head], ex);
        }
    }
}

// ---------------- K3: finalize ----------------------------------------------
__global__ void finalize_kernel(float* __restrict__ out) {
    int i = blockIdx.x * blockDim.x + threadIdx.x;
    if (i >= NODES * OC) return;
    int n = i >> 6;
    int c = i & 63;
    float d0 = g_denom[n * 2 + 0] + 1e-16f;
    float d1 = g_denom[n * 2 + 1] + 1e-16f;
    float v = 0.5f * (g_agg[(size_t)n * HC + c] / d0 + g_agg[(size_t)n * HC + 64 + c] / d1);
    out[i] = v + g_xs[i];
}

// ---------------- launch ------------------------------------------------------
extern "C" void kernel_launch(void* const* d_in, const int* in_sizes, int n_in,
                              void* d_out, int out_size) {
    const float* x        = (const float*)d_in[0];
    const float* edge_attr= (const float*)d_in[1];
    const float* W_msg    = (const float*)d_in[2];
    const float* b_msg    = (const float*)d_in[3];
    const float* W_edge   = (const float*)d_in[4];
    const float* b_edge   = (const float*)d_in[5];
    const float* W_self   = (const float*)d_in[6];
    const float* b_self   = (const float*)d_in[7];
    const float* att      = (const float*)d_in[8];
    const int*   ei       = (const int*)d_in[9];
    const int* srcI = ei;
    const int* dstI = ei + EDGES;

    float* out = (float*)d_out;
    float* le_out;
    bool le_in_out = (out_size >= NODES * OC + (long long)EDGES * HC);
    if (le_in_out) {
        le_out = out + (size_t)NODES * OC;
    } else {
        void* p = nullptr;
        cudaGetSymbolAddress(&p, g_le_fallback);
        le_out = (float*)p;
    }

    cudaFuncSetAttribute(node_kernel, cudaFuncAttributeMaxDynamicSharedMemorySize, 131072);
    cudaFuncSetAttribute(edge_kernel, cudaFuncAttributeMaxDynamicSharedMemorySize, SM_TOTAL);

    init_kernel<<<(NODES * HC + 255) / 256, 256>>>();
    prep_kernel<<<32, 256>>>(W_edge);
    node_kernel<<<NODES / 64, 256, 131072>>>(x, W_msg, b_msg, W_self, b_self);
    edge_kernel<<<EDGES / 128, 256, SM_TOTAL>>>(edge_attr, b_edge, att, srcI, dstI, le_out);
    finalize_kernel<<<(NODES * OC + 255) / 256, 256>>>(out);
}

// round 7
// speedup vs baseline: 1.1946x; 1.1946x over previous
#include <cuda_runtime.h>
#include <cuda_bf16.h>
#include <cstdint>

#define NODES 40000
#define EDGES 640000
#define DIN   128
#define HC    128
#define OC    64

typedef unsigned long long ull;

// single dynamic-shared declaration for the whole TU
extern __shared__ char dynsm[];

// ---------------- device scratch ------------------------------------------
__device__ float g_xm[(size_t)NODES * HC];
__device__ float g_xs[(size_t)NODES * OC];
__device__ float g_denom[(size_t)NODES * 2];
__device__ float g_agg[(size_t)NODES * HC];
__device__ float g_le_fallback[(size_t)EDGES * HC];
// W_edge^T split into bf16 hi/lo: [n][k-pair] padded row stride 68 words
__device__ __align__(16) uint32_t g_Bhi[128 * 68];
__device__ __align__(16) uint32_t g_Blo[128 * 68];

// ---------------- helpers ----------------------------------------------------
__device__ __forceinline__ void red_add_v4(float* p, float a, float b, float c, float d) {
    asm volatile("red.global.add.v4.f32 [%0], {%1,%2,%3,%4};"
                 :: "l"(p), "f"(a), "f"(b), "f"(c), "f"(d) : "memory");
}
__device__ __forceinline__ void red_add_f32(float* p, float v) {
    asm volatile("red.global.add.f32 [%0], %1;" :: "l"(p), "f"(v) : "memory");
}
// m16n8k16 row.col bf16 MMA, f32 accumulate (base-target HMMA)
__device__ __forceinline__ void mma_bf16(float* c, const uint32_t* a, const uint32_t* b) {
    asm volatile("mma.sync.aligned.m16n8k16.row.col.f32.bf16.bf16.f32 "
                 "{%0,%1,%2,%3}, {%4,%5,%6,%7}, {%8,%9}, {%0,%1,%2,%3};"
                 : "+f"(c[0]), "+f"(c[1]), "+f"(c[2]), "+f"(c[3])
                 : "r"(a[0]), "r"(a[1]), "r"(a[2]), "r"(a[3]), "r"(b[0]), "r"(b[1]));
}
__device__ __forceinline__ uint32_t pack_bf16x2_split(float v0, float v1, uint32_t& lo) {
    __nv_bfloat16 h0 = __float2bfloat16_rn(v0);
    __nv_bfloat16 h1 = __float2bfloat16_rn(v1);
    __nv_bfloat16 l0 = __float2bfloat16_rn(v0 - __bfloat162float(h0));
    __nv_bfloat16 l1 = __float2bfloat16_rn(v1 - __bfloat162float(h1));
    lo = (uint32_t)__bfloat16_as_ushort(l0) | ((uint32_t)__bfloat16_as_ushort(l1) << 16);
    return (uint32_t)__bfloat16_as_ushort(h0) | ((uint32_t)__bfloat16_as_ushort(h1) << 16);
}

// ---------------- K0: init --------------------------------------------------
__global__ void init_kernel() {
    int i = blockIdx.x * blockDim.x + threadIdx.x;
    if (i < NODES * HC) g_agg[i] = 0.0f;
    if (i < NODES * 2)  g_denom[i] = 0.0f;
}

// ---------------- prep: W_edge^T -> bf16 hi/lo padded [n][k] images ----------
__global__ void prep_kernel(const float* __restrict__ W_edge) {
    int p = blockIdx.x * 256 + threadIdx.x;   // 8192 = 128 n x 64 k-pairs
    if (p >= 8192) return;
    int n  = p >> 6;
    int kp = p & 63;
    int k  = kp * 2;
    uint32_t lo;
    uint32_t hi = pack_bf16x2_split(W_edge[k * HC + n], W_edge[(k + 1) * HC + n], lo);
    g_Bhi[n * 68 + kp] = hi;
    g_Blo[n * 68 + kp] = lo;
}

// ---------------- K1: node GEMMs (known-good) --------------------------------
__global__ void node_kernel(const float* __restrict__ x,
                            const float* __restrict__ W_msg,
                            const float* __restrict__ b_msg,
                            const float* __restrict__ W_self,
                            const float* __restrict__ b_self) {
    float* smf = (float*)dynsm;
    float* Xs = smf;
    float* Wm = smf + 64 * 128;
    float* Wf = Wm + 128 * 128;
    int tid = threadIdx.x;

    const float4* xg = (const float4*)(x + (size_t)blockIdx.x * 64 * DIN);
#pragma unroll
    for (int i = 0; i < 8; i++)  ((float4*)Xs)[tid + i * 256] = xg[tid + i * 256];
#pragma unroll
    for (int i = 0; i < 16; i++) ((float4*)Wm)[tid + i * 256] = ((const float4*)W_msg)[tid + i * 256];
#pragma unroll
    for (int i = 0; i < 8; i++)  ((float4*)Wf)[tid + i * 256] = ((const float4*)W_self)[tid + i * 256];
    __syncthreads();

    int lane = tid & 31, ty = tid >> 5;
    int lane4 = lane * 4;
    const float* Xr = Xs + ty * 8 * DIN;
    {
        float acc[8][4];
#pragma unroll
        for (int r = 0; r < 8; r++) { acc[r][0] = acc[r][1] = acc[r][2] = acc[r][3] = 0.f; }
#pragma unroll 4
        for (int k = 0; k < 128; k++) {
            float4 bq = *(float4*)(Wm + k * 128 + lane4);
#pragma unroll
            for (int r = 0; r < 8; r++) {
                float av = Xr[r * DIN + k];
                acc[r][0] += av * bq.x; acc[r][1] += av * bq.y;
                acc[r][2] += av * bq.z; acc[r][3] += av * bq.w;
            }
        }
        float4 bm = *(const float4*)(b_msg + lane4);
#pragma unroll
        for (int r = 0; r < 8; r++) {
            int n = blockIdx.x * 64 + ty * 8 + r;
            float4 v; v.x = acc[r][0] + bm.x; v.y = acc[r][1] + bm.y;
            v.z = acc[r][2] + bm.z; v.w = acc[r][3] + bm.w;
            *(float4*)(g_xm + (size_t)n * HC + lane4) = v;
        }
    }
    {
        int lane2 = lane * 2;
        float acc[8][2];
#pragma unroll
        for (int r = 0; r < 8; r++) { acc[r][0] = acc[r][1] = 0.f; }
#pragma unroll 4
        for (int k = 0; k < 128; k++) {
            float2 bq = *(float2*)(Wf + k * 64 + lane2);
#pragma unroll
            for (int r = 0; r < 8; r++) {
                float av = Xr[r * DIN + k];
                acc[r][0] += av * bq.x; acc[r][1] += av * bq.y;
            }
        }
        float2 bs = *(const float2*)(b_self + lane2);
#pragma unroll
        for (int r = 0; r < 8; r++) {
            int n = blockIdx.x * 64 + ty * 8 + r;
            float2 v; v.x = acc[r][0] + bs.x; v.y = acc[r][1] + bs.y;
            *(float2*)(g_xs + (size_t)n * OC + lane2) = v;
        }
    }
}

// ---------------- K2: HMMA edge GEMM + fused attention scatter ---------------
// Tile = 64 edges x 128 cols, K = 128. bf16 3-term split on mma.sync m16n8k16.
// 2 CTAs/SM (16 warps) for latency hiding.
// 8 warps: warp w -> rows [(w>>1)*16, +16), cols [(w&1)*64, +64).
// smem (bytes):
//   16     : b_edge bias (512B)
//   1024   : A_hi  (17408 = 64 rows x 68 words)
//   18432  : A_lo  (17408)
//   35840  : B_hi  (34816)
//   70656  : B_lo  (34816)  -> total 105472
//   le_stage aliases 1024.. (64 rows x 132 words = 33792B <= 34816) after MMA
#define SM_AHI   1024
#define SM_ALO   18432
#define SM_BHI   35840
#define SM_BLO   70656
#define SM_TOTAL 105472
#define LE_STRIDE 132

__global__ void __launch_bounds__(256, 2) edge_kernel(
        const float* __restrict__ edge_attr,
        const float* __restrict__ b_edge,
        const float* __restrict__ att,
        const int*   __restrict__ srcIdx,
        const int*   __restrict__ dstIdx,
        float* __restrict__ le_out) {
    char* sm = dynsm;
    int tid = threadIdx.x;
    int wid = tid >> 5;
    int lane = tid & 31;
    float* b_s = (float*)(sm + 16);
    float* le_stage = (float*)(sm + SM_AHI);
    uint32_t* Ah32 = (uint32_t*)(sm + SM_AHI);
    uint32_t* Al32 = (uint32_t*)(sm + SM_ALO);
    uint32_t* Bh32 = (uint32_t*)(sm + SM_BHI);
    uint32_t* Bl32 = (uint32_t*)(sm + SM_BLO);

    if (tid < 128) b_s[tid] = b_edge[tid];

    // B images from gmem (L2-hot): 2176 uint4 each
    {
        const uint4* bh = (const uint4*)g_Bhi;
        const uint4* bl = (const uint4*)g_Blo;
        uint4* dh = (uint4*)Bh32;
        uint4* dl = (uint4*)Bl32;
#pragma unroll
        for (int i = 0; i < 9; i++) {
            int idx = tid + i * 256;
            if (idx < 2176) { dh[idx] = bh[idx]; dl[idx] = bl[idx]; }
        }
    }

    // A tile: 64 edges x 128 f32 -> split bf16 hi/lo, padded stride 68 words
    {
        const float2* src = (const float2*)(edge_attr + (size_t)blockIdx.x * 64 * DIN);
#pragma unroll
        for (int i = 0; i < 16; i++) {
            int p = tid + i * 256;            // pair index 0..4095
            int row = p >> 6;
            int kp  = p & 63;
            float2 v = src[p];
            uint32_t lo;
            uint32_t hi = pack_bf16x2_split(v.x, v.y, lo);
            Ah32[row * 68 + kp] = hi;
            Al32[row * 68 + kp] = lo;
        }
    }
    __syncthreads();

    // ---- MMA mainloop ----
    int rowg = wid >> 1;          // 0..3  -> rows rowg*16..+16
    int colg = wid & 1;           // 0..1  -> cols colg*64..+64
    int r   = lane >> 2;          // 0..7
    int tig = lane & 3;           // 0..3

    float acc[8][4];
#pragma unroll
    for (int nf = 0; nf < 8; nf++)
#pragma unroll
        for (int q = 0; q < 4; q++) acc[nf][q] = 0.f;

#pragma unroll
    for (int ks = 0; ks < 8; ks++) {
        int kw = ks * 8 + tig;
        uint32_t ah[4], al[4];
        {
            int base = (rowg * 16 + r) * 68 + kw;
            ah[0] = Ah32[base];            ah[1] = Ah32[base + 8 * 68];
            ah[2] = Ah32[base + 4];        ah[3] = Ah32[base + 8 * 68 + 4];
            al[0] = Al32[base];            al[1] = Al32[base + 8 * 68];
            al[2] = Al32[base + 4];        al[3] = Al32[base + 8 * 68 + 4];
        }
#pragma unroll
        for (int nf = 0; nf < 8; nf++) {
            int nb = (colg * 64 + nf * 8 + r) * 68 + kw;
            uint32_t bh[2] = { Bh32[nb], Bh32[nb + 4] };
            uint32_t bl[2] = { Bl32[nb], Bl32[nb + 4] };
            mma_bf16(acc[nf], ah, bh);
            mma_bf16(acc[nf], ah, bl);
            mma_bf16(acc[nf], al, bh);
        }
    }
    __syncthreads();   // all smem A reads complete before le_stage overwrite

    // ---- epilogue: bias add -> le_stage (aliases A region) ----
#pragma unroll
    for (int nf = 0; nf < 8; nf++) {
        int row = rowg * 16 + r;
        int col = colg * 64 + nf * 8 + tig * 2;
        float bb0 = b_s[col], bb1 = b_s[col + 1];
        float2 v0; v0.x = acc[nf][0] + bb0; v0.y = acc[nf][1] + bb1;
        float2 v1; v1.x = acc[nf][2] + bb0; v1.y = acc[nf][3] + bb1;
        *(float2*)(le_stage + (size_t)row * LE_STRIDE + col) = v0;
        *(float2*)(le_stage + (size_t)(row + 8) * LE_STRIDE + col) = v1;
    }
    __syncthreads();

    // ---- pass A: coalesced le store to gmem ----
    {
        float* lo = le_out + (size_t)blockIdx.x * 64 * HC;
#pragma unroll
        for (int i = 0; i < 32; i++) {
            int idx = tid + i * 256;           // 0..8191
            int row = idx >> 7, col = idx & 127;
            lo[idx] = le_stage[(size_t)row * LE_STRIDE + col];
        }
    }

    // ---- pass B: attention + exp + scatter. 8 warps x 8 edges ----
    {
        int lane4 = lane * 4;
        float4 attv = *(const float4*)(att + lane4);
        int head = lane >> 4;
#pragma unroll
        for (int j = 0; j < 8; j++) {
            int el = wid * 8 + j;
            int e = blockIdx.x * 64 + el;
            int s = srcIdx[e];
            int d = dstIdx[e];
            float4 lv = *(float4*)(le_stage + (size_t)el * LE_STRIDE + lane4);
            float4 xv = *(const float4*)(g_xm + (size_t)s * HC + lane4);
            float m0 = lv.x + xv.x, m1 = lv.y + xv.y, m2 = lv.z + xv.z, m3 = lv.w + xv.w;
            float p = m0 * attv.x + m1 * attv.y + m2 * attv.z + m3 * attv.w;
            p += __shfl_xor_sync(0xffffffffu, p, 1);
            p += __shfl_xor_sync(0xffffffffu, p, 2);
            p += __shfl_xor_sync(0xffffffffu, p, 4);
            p += __shfl_xor_sync(0xffffffffu, p, 8);
            float lr = p > 0.0f ? p : 0.2f * p;
            float ex = __expf(lr);
            red_add_v4(g_agg + (size_t)d * HC + lane4, m0 * ex, m1 * ex, m2 * ex, m3 * ex);
            if ((lane & 15) == 0) red_add_f32(&g_denom[d * 2 + head], ex);
        }
    }
}

// ---------------- K3: finalize ----------------------------------------------
__global__ void finalize_kernel(float* __restrict__ out) {
    int i = blockIdx.x * blockDim.x + threadIdx.x;
    if (i >= NODES * OC) return;
    int n = i >> 6;
    int c = i & 63;
    float d0 = g_denom[n * 2 + 0] + 1e-16f;
    float d1 = g_denom[n * 2 + 1] + 1e-16f;
    float v = 0.5f * (g_agg[(size_t)n * HC + c] / d0 + g_agg[(size_t)n * HC + 64 + c] / d1);
    out[i] = v + g_xs[i];
}

// ---------------- launch ------------------------------------------------------
extern "C" void kernel_launch(void* const* d_in, const int* in_sizes, int n_in,
                              void* d_out, int out_size) {
    const float* x        = (const float*)d_in[0];
    const float* edge_attr= (const float*)d_in[1];
    const float* W_msg    = (const float*)d_in[2];
    const float* b_msg    = (const float*)d_in[3];
    const float* W_edge   = (const float*)d_in[4];
    const float* b_edge   = (const float*)d_in[5];
    const float* W_self   = (const float*)d_in[6];
    const float* b_self   = (const float*)d_in[7];
    const float* att      = (const float*)d_in[8];
    const int*   ei       = (const int*)d_in[9];
    const int* srcI = ei;
    const int* dstI = ei + EDGES;

    float* out = (float*)d_out;
    float* le_out;
    bool le_in_out = (out_size >= NODES * OC + (long long)EDGES * HC);
    if (le_in_out) {
        le_out = out + (size_t)NODES * OC;
    } else {
        void* p = nullptr;
        cudaGetSymbolAddress(&p, g_le_fallback);
        le_out = (float*)p;
    }

    cudaFuncSetAttribute(node_kernel, cudaFuncAttributeMaxDynamicSharedMemorySize, 131072);
    cudaFuncSetAttribute(edge_kernel, cudaFuncAttributeMaxDynamicSharedMemorySize, SM_TOTAL);

    init_kernel<<<(NODES * HC + 255) / 256, 256>>>();
    prep_kernel<<<32, 256>>>(W_edge);
    node_kernel<<<NODES / 64, 256, 131072>>>(x, W_msg, b_msg, W_self, b_self);
    edge_kernel<<<EDGES / 64, 256, SM_TOTAL>>>(edge_attr, b_edge, att, srcI, dstI, le_out);
    finalize_kernel<<<(NODES * OC + 255) / 256, 256>>>(out);
}

// round 8
// speedup vs baseline: 1.3083x; 1.0951x over previous
#include <cuda_runtime.h>
#include <cuda_bf16.h>
#include <cstdint>

#define NODES 40000
#define EDGES 640000
#define DIN   128
#define HC    128
#define OC    64
#define NTILES 10000   // 64 edges per tile

typedef unsigned long long ull;

// single dynamic-shared declaration for the whole TU
extern __shared__ char dynsm[];

// ---------------- device scratch ------------------------------------------
__device__ float g_xm[(size_t)NODES * HC];
__device__ float g_xs[(size_t)NODES * OC];
__device__ float g_denom[(size_t)NODES * 2];
__device__ float g_agg[(size_t)NODES * HC];
__device__ float g_le_fallback[(size_t)EDGES * HC];
// W_edge^T split into bf16 hi/lo: [n][k-pair] padded row stride 68 words
__device__ __align__(16) uint32_t g_Bhi[128 * 68];
__device__ __align__(16) uint32_t g_Blo[128 * 68];

// ---------------- helpers ----------------------------------------------------
__device__ __forceinline__ void red_add_v4(float* p, float a, float b, float c, float d) {
    asm volatile("red.global.add.v4.f32 [%0], {%1,%2,%3,%4};"
                 :: "l"(p), "f"(a), "f"(b), "f"(c), "f"(d) : "memory");
}
__device__ __forceinline__ void red_add_f32(float* p, float v) {
    asm volatile("red.global.add.f32 [%0], %1;" :: "l"(p), "f"(v) : "memory");
}
// m16n8k16 row.col bf16 MMA, f32 accumulate (base-target HMMA)
__device__ __forceinline__ void mma_bf16(float* c, const uint32_t* a, const uint32_t* b) {
    asm volatile("mma.sync.aligned.m16n8k16.row.col.f32.bf16.bf16.f32 "
                 "{%0,%1,%2,%3}, {%4,%5,%6,%7}, {%8,%9}, {%0,%1,%2,%3};"
                 : "+f"(c[0]), "+f"(c[1]), "+f"(c[2]), "+f"(c[3])
                 : "r"(a[0]), "r"(a[1]), "r"(a[2]), "r"(a[3]), "r"(b[0]), "r"(b[1]));
}
__device__ __forceinline__ uint32_t pack_bf16x2_split(float v0, float v1, uint32_t& lo) {
    __nv_bfloat16 h0 = __float2bfloat16_rn(v0);
    __nv_bfloat16 h1 = __float2bfloat16_rn(v1);
    __nv_bfloat16 l0 = __float2bfloat16_rn(v0 - __bfloat162float(h0));
    __nv_bfloat16 l1 = __float2bfloat16_rn(v1 - __bfloat162float(h1));
    lo = (uint32_t)__bfloat16_as_ushort(l0) | ((uint32_t)__bfloat16_as_ushort(l1) << 16);
    return (uint32_t)__bfloat16_as_ushort(h0) | ((uint32_t)__bfloat16_as_ushort(h1) << 16);
}

// ---------------- K0: init --------------------------------------------------
__global__ void init_kernel() {
    int i = blockIdx.x * blockDim.x + threadIdx.x;
    if (i < NODES * HC) g_agg[i] = 0.0f;
    if (i < NODES * 2)  g_denom[i] = 0.0f;
}

// ---------------- prep: W_edge^T -> bf16 hi/lo padded [n][k] images ----------
__global__ void prep_kernel(const float* __restrict__ W_edge) {
    int p = blockIdx.x * 256 + threadIdx.x;   // 8192 = 128 n x 64 k-pairs
    if (p >= 8192) return;
    int n  = p >> 6;
    int kp = p & 63;
    int k  = kp * 2;
    uint32_t lo;
    uint32_t hi = pack_bf16x2_split(W_edge[k * HC + n], W_edge[(k + 1) * HC + n], lo);
    g_Bhi[n * 68 + kp] = hi;
    g_Blo[n * 68 + kp] = lo;
}

// ---------------- K1: node GEMMs (known-good) --------------------------------
__global__ void node_kernel(const float* __restrict__ x,
                            const float* __restrict__ W_msg,
                            const float* __restrict__ b_msg,
                            const float* __restrict__ W_self,
                            const float* __restrict__ b_self) {
    float* smf = (float*)dynsm;
    float* Xs = smf;
    float* Wm = smf + 64 * 128;
    float* Wf = Wm + 128 * 128;
    int tid = threadIdx.x;

    const float4* xg = (const float4*)(x + (size_t)blockIdx.x * 64 * DIN);
#pragma unroll
    for (int i = 0; i < 8; i++)  ((float4*)Xs)[tid + i * 256] = xg[tid + i * 256];
#pragma unroll
    for (int i = 0; i < 16; i++) ((float4*)Wm)[tid + i * 256] = ((const float4*)W_msg)[tid + i * 256];
#pragma unroll
    for (int i = 0; i < 8; i++)  ((float4*)Wf)[tid + i * 256] = ((const float4*)W_self)[tid + i * 256];
    __syncthreads();

    int lane = tid & 31, ty = tid >> 5;
    int lane4 = lane * 4;
    const float* Xr = Xs + ty * 8 * DIN;
    {
        float acc[8][4];
#pragma unroll
        for (int r = 0; r < 8; r++) { acc[r][0] = acc[r][1] = acc[r][2] = acc[r][3] = 0.f; }
#pragma unroll 4
        for (int k = 0; k < 128; k++) {
            float4 bq = *(float4*)(Wm + k * 128 + lane4);
#pragma unroll
            for (int r = 0; r < 8; r++) {
                float av = Xr[r * DIN + k];
                acc[r][0] += av * bq.x; acc[r][1] += av * bq.y;
                acc[r][2] += av * bq.z; acc[r][3] += av * bq.w;
            }
        }
        float4 bm = *(const float4*)(b_msg + lane4);
#pragma unroll
        for (int r = 0; r < 8; r++) {
            int n = blockIdx.x * 64 + ty * 8 + r;
            float4 v; v.x = acc[r][0] + bm.x; v.y = acc[r][1] + bm.y;
            v.z = acc[r][2] + bm.z; v.w = acc[r][3] + bm.w;
            *(float4*)(g_xm + (size_t)n * HC + lane4) = v;
        }
    }
    {
        int lane2 = lane * 2;
        float acc[8][2];
#pragma unroll
        for (int r = 0; r < 8; r++) { acc[r][0] = acc[r][1] = 0.f; }
#pragma unroll 4
        for (int k = 0; k < 128; k++) {
            float2 bq = *(float2*)(Wf + k * 64 + lane2);
#pragma unroll
            for (int r = 0; r < 8; r++) {
                float av = Xr[r * DIN + k];
                acc[r][0] += av * bq.x; acc[r][1] += av * bq.y;
            }
        }
        float2 bs = *(const float2*)(b_self + lane2);
#pragma unroll
        for (int r = 0; r < 8; r++) {
            int n = blockIdx.x * 64 + ty * 8 + r;
            float2 v; v.x = acc[r][0] + bs.x; v.y = acc[r][1] + bs.y;
            *(float2*)(g_xs + (size_t)n * OC + lane2) = v;
        }
    }
}

// ---------------- K2: persistent HMMA edge GEMM + fused scatter --------------
// Persistent: 296 CTAs (2/SM), each loads B once and loops over tiles of 64
// edges. A for the NEXT tile is prefetched into registers during the current
// tile's MMA phase (DRAM latency hidden behind tensor work).
// smem (bytes):
//   16    : b_edge bias (512B)
//   1024  : A_hi (17408 = 64 rows x 68 words)   \ le_stage (64 x 132 words =
//   18432 : A_lo (17408)                        /  33792B) aliases A after MMA
//   35840 : B_hi (34816)
//   70656 : B_lo (34816)  -> total 105472  (2 CTAs/SM)
#define SM_AHI   1024
#define SM_ALO   18432
#define SM_BHI   35840
#define SM_BLO   70656
#define SM_TOTAL 105472
#define LE_STRIDE 132

__global__ void __launch_bounds__(256, 2) edge_kernel(
        const float* __restrict__ edge_attr,
        const float* __restrict__ b_edge,
        const float* __restrict__ att,
        const int*   __restrict__ srcIdx,
        const int*   __restrict__ dstIdx,
        float* __restrict__ le_out) {
    char* sm = dynsm;
    int tid = threadIdx.x;
    int wid = tid >> 5;
    int lane = tid & 31;
    float* b_s = (float*)(sm + 16);
    float* le_stage = (float*)(sm + SM_AHI);
    uint32_t* Ah32 = (uint32_t*)(sm + SM_AHI);
    uint32_t* Al32 = (uint32_t*)(sm + SM_ALO);
    uint32_t* Bh32 = (uint32_t*)(sm + SM_BHI);
    uint32_t* Bl32 = (uint32_t*)(sm + SM_BLO);

    // ---- prologue (once per CTA) ----
    if (tid < 128) b_s[tid] = b_edge[tid];
    {
        const uint4* bh = (const uint4*)g_Bhi;
        const uint4* bl = (const uint4*)g_Blo;
        uint4* dh = (uint4*)Bh32;
        uint4* dl = (uint4*)Bl32;
#pragma unroll
        for (int i = 0; i < 9; i++) {
            int idx = tid + i * 256;
            if (idx < 2176) { dh[idx] = bh[idx]; dl[idx] = bl[idx]; }
        }
    }

    int rowg = wid >> 1;          // 0..3 -> rows rowg*16..+16
    int colg = wid & 1;           // 0..1 -> cols colg*64..+64
    int r   = lane >> 2;          // 0..7
    int tig = lane & 3;           // 0..3
    int lane4 = lane * 4;
    float4 attv = *(const float4*)(att + lane4);
    int head = lane >> 4;

    int t = blockIdx.x;
    if (t >= NTILES) return;

    // first tile's raw A into registers
    float2 ar[16];
    {
        const float2* src = (const float2*)(edge_attr + (size_t)t * 64 * DIN);
#pragma unroll
        for (int i = 0; i < 16; i++) ar[i] = src[tid + i * 256];
    }

    while (true) {
        // ---- convert regs -> A smem (hi/lo split) ----
#pragma unroll
        for (int i = 0; i < 16; i++) {
            int p = tid + i * 256;            // 0..4095
            int row = p >> 6;
            int kp  = p & 63;
            uint32_t lo;
            uint32_t hi = pack_bf16x2_split(ar[i].x, ar[i].y, lo);
            Ah32[row * 68 + kp] = hi;
            Al32[row * 68 + kp] = lo;
        }
        __syncthreads();

        // ---- prefetch next tile's raw A (latency hides behind MMA) ----
        int tn = t + gridDim.x;
        if (tn < NTILES) {
            const float2* src = (const float2*)(edge_attr + (size_t)tn * 64 * DIN);
#pragma unroll
            for (int i = 0; i < 16; i++) ar[i] = src[tid + i * 256];
        }

        // ---- MMA mainloop ----
        float acc[8][4];
#pragma unroll
        for (int nf = 0; nf < 8; nf++)
#pragma unroll
            for (int q = 0; q < 4; q++) acc[nf][q] = 0.f;

#pragma unroll
        for (int ks = 0; ks < 8; ks++) {
            int kw = ks * 8 + tig;
            uint32_t ah[4], al[4];
            {
                int base = (rowg * 16 + r) * 68 + kw;
                ah[0] = Ah32[base];        ah[1] = Ah32[base + 8 * 68];
                ah[2] = Ah32[base + 4];    ah[3] = Ah32[base + 8 * 68 + 4];
                al[0] = Al32[base];        al[1] = Al32[base + 8 * 68];
                al[2] = Al32[base + 4];    al[3] = Al32[base + 8 * 68 + 4];
            }
#pragma unroll
            for (int nf = 0; nf < 8; nf++) {
                int nb = (colg * 64 + nf * 8 + r) * 68 + kw;
                uint32_t bh[2] = { Bh32[nb], Bh32[nb + 4] };
                uint32_t bl[2] = { Bl32[nb], Bl32[nb + 4] };
                mma_bf16(acc[nf], ah, bh);
                mma_bf16(acc[nf], ah, bl);
                mma_bf16(acc[nf], al, bh);
            }
        }
        __syncthreads();   // A smem reads complete before le_stage overwrite

        // ---- epilogue: bias add -> le_stage (aliases A) ----
#pragma unroll
        for (int nf = 0; nf < 8; nf++) {
            int row = rowg * 16 + r;
            int col = colg * 64 + nf * 8 + tig * 2;
            float bb0 = b_s[col], bb1 = b_s[col + 1];
            float2 v0; v0.x = acc[nf][0] + bb0; v0.y = acc[nf][1] + bb1;
            float2 v1; v1.x = acc[nf][2] + bb0; v1.y = acc[nf][3] + bb1;
            *(float2*)(le_stage + (size_t)row * LE_STRIDE + col) = v0;
            *(float2*)(le_stage + (size_t)(row + 8) * LE_STRIDE + col) = v1;
        }
        __syncthreads();

        // ---- coalesced le store ----
        {
            float* lo = le_out + (size_t)t * 64 * HC;
#pragma unroll
            for (int i = 0; i < 32; i++) {
                int idx = tid + i * 256;       // 0..8191
                int row = idx >> 7, col = idx & 127;
                lo[idx] = le_stage[(size_t)row * LE_STRIDE + col];
            }
        }

        // ---- attention + exp + scatter: 8 warps x 8 edges ----
#pragma unroll
        for (int j = 0; j < 8; j++) {
            int el = wid * 8 + j;
            int e = t * 64 + el;
            int s = srcIdx[e];
            int d = dstIdx[e];
            float4 lv = *(float4*)(le_stage + (size_t)el * LE_STRIDE + lane4);
            float4 xv = *(const float4*)(g_xm + (size_t)s * HC + lane4);
            float m0 = lv.x + xv.x, m1 = lv.y + xv.y, m2 = lv.z + xv.z, m3 = lv.w + xv.w;
            float p = m0 * attv.x + m1 * attv.y + m2 * attv.z + m3 * attv.w;
            p += __shfl_xor_sync(0xffffffffu, p, 1);
            p += __shfl_xor_sync(0xffffffffu, p, 2);
            p += __shfl_xor_sync(0xffffffffu, p, 4);
            p += __shfl_xor_sync(0xffffffffu, p, 8);
            float lr = p > 0.0f ? p : 0.2f * p;
            float ex = __expf(lr);
            red_add_v4(g_agg + (size_t)d * HC + lane4, m0 * ex, m1 * ex, m2 * ex, m3 * ex);
            if ((lane & 15) == 0) red_add_f32(&g_denom[d * 2 + head], ex);
        }

        if (tn >= NTILES) break;
        t = tn;
        __syncthreads();   // le_stage reads done before next convert overwrites
    }
}

// ---------------- K3: finalize ----------------------------------------------
__global__ void finalize_kernel(float* __restrict__ out) {
    int i = blockIdx.x * blockDim.x + threadIdx.x;
    if (i >= NODES * OC) return;
    int n = i >> 6;
    int c = i & 63;
    float d0 = g_denom[n * 2 + 0] + 1e-16f;
    float d1 = g_denom[n * 2 + 1] + 1e-16f;
    float v = 0.5f * (g_agg[(size_t)n * HC + c] / d0 + g_agg[(size_t)n * HC + 64 + c] / d1);
    out[i] = v + g_xs[i];
}

// ---------------- launch ------------------------------------------------------
extern "C" void kernel_launch(void* const* d_in, const int* in_sizes, int n_in,
                              void* d_out, int out_size) {
    const float* x        = (const float*)d_in[0];
    const float* edge_attr= (const float*)d_in[1];
    const float* W_msg    = (const float*)d_in[2];
    const float* b_msg    = (const float*)d_in[3];
    const float* W_edge   = (const float*)d_in[4];
    const float* b_edge   = (const float*)d_in[5];
    const float* W_self   = (const float*)d_in[6];
    const float* b_self   = (const float*)d_in[7];
    const float* att      = (const float*)d_in[8];
    const int*   ei       = (const int*)d_in[9];
    const int* srcI = ei;
    const int* dstI = ei + EDGES;

    float* out = (float*)d_out;
    float* le_out;
    bool le_in_out = (out_size >= NODES * OC + (long long)EDGES * HC);
    if (le_in_out) {
        le_out = out + (size_t)NODES * OC;
    } else {
        void* p = nullptr;
        cudaGetSymbolAddress(&p, g_le_fallback);
        le_out = (float*)p;
    }

    cudaFuncSetAttribute(node_kernel, cudaFuncAttributeMaxDynamicSharedMemorySize, 131072);
    cudaFuncSetAttribute(edge_kernel, cudaFuncAttributeMaxDynamicSharedMemorySize, SM_TOTAL);

    init_kernel<<<(NODES * HC + 255) / 256, 256>>>();
    prep_kernel<<<32, 256>>>(W_edge);
    node_kernel<<<NODES / 64, 256, 131072>>>(x, W_msg, b_msg, W_self, b_self);
    edge_kernel<<<296, 256, SM_TOTAL>>>(edge_attr, b_edge, att, srcI, dstI, le_out);
    finalize_kernel<<<(NODES * OC + 255) / 256, 256>>>(out);
}

// round 9
// speedup vs baseline: 1.3995x; 1.0697x over previous
#include <cuda_runtime.h>
#include <cuda_bf16.h>
#include <cstdint>

#define NODES 40000
#define EDGES 640000
#define DIN   128
#define HC    128
#define OC    64
#define NTILES 10000   // 64 edges per tile

typedef unsigned long long ull;

// single dynamic-shared declaration for the whole TU
extern __shared__ char dynsm[];

// ---------------- device scratch ------------------------------------------
__device__ float g_xm[(size_t)NODES * HC];
__device__ float g_xs[(size_t)NODES * OC];
__device__ float g_denom[(size_t)NODES * 2];
__device__ float g_agg[(size_t)NODES * HC];
__device__ float g_le_fallback[(size_t)EDGES * HC];
// W_edge^T split into bf16 hi/lo: [n][k-pair] padded row stride 68 words
__device__ __align__(16) uint32_t g_Bhi[128 * 68];
__device__ __align__(16) uint32_t g_Blo[128 * 68];

// ---------------- helpers ----------------------------------------------------
__device__ __forceinline__ void red_add_v2(float* p, float a, float b) {
    asm volatile("red.global.add.v2.f32 [%0], {%1,%2};"
                 :: "l"(p), "f"(a), "f"(b) : "memory");
}
__device__ __forceinline__ void red_add_f32(float* p, float v) {
    asm volatile("red.global.add.f32 [%0], %1;" :: "l"(p), "f"(v) : "memory");
}
// m16n8k16 row.col bf16 MMA, f32 accumulate (base-target HMMA)
__device__ __forceinline__ void mma_bf16(float* c, const uint32_t* a, const uint32_t* b) {
    asm volatile("mma.sync.aligned.m16n8k16.row.col.f32.bf16.bf16.f32 "
                 "{%0,%1,%2,%3}, {%4,%5,%6,%7}, {%8,%9}, {%0,%1,%2,%3};"
                 : "+f"(c[0]), "+f"(c[1]), "+f"(c[2]), "+f"(c[3])
                 : "r"(a[0]), "r"(a[1]), "r"(a[2]), "r"(a[3]), "r"(b[0]), "r"(b[1]));
}
__device__ __forceinline__ uint32_t pack_bf16x2_split(float v0, float v1, uint32_t& lo) {
    __nv_bfloat16 h0 = __float2bfloat16_rn(v0);
    __nv_bfloat16 h1 = __float2bfloat16_rn(v1);
    __nv_bfloat16 l0 = __float2bfloat16_rn(v0 - __bfloat162float(h0));
    __nv_bfloat16 l1 = __float2bfloat16_rn(v1 - __bfloat162float(h1));
    lo = (uint32_t)__bfloat16_as_ushort(l0) | ((uint32_t)__bfloat16_as_ushort(l1) << 16);
    return (uint32_t)__bfloat16_as_ushort(h0) | ((uint32_t)__bfloat16_as_ushort(h1) << 16);
}

// ---------------- K0: init --------------------------------------------------
__global__ void init_kernel() {
    int i = blockIdx.x * blockDim.x + threadIdx.x;
    if (i < NODES * HC) g_agg[i] = 0.0f;
    if (i < NODES * 2)  g_denom[i] = 0.0f;
}

// ---------------- prep: W_edge^T -> bf16 hi/lo padded [n][k] images ----------
__global__ void prep_kernel(const float* __restrict__ W_edge) {
    int p = blockIdx.x * 256 + threadIdx.x;   // 8192 = 128 n x 64 k-pairs
    if (p >= 8192) return;
    int n  = p >> 6;
    int kp = p & 63;
    int k  = kp * 2;
    uint32_t lo;
    uint32_t hi = pack_bf16x2_split(W_edge[k * HC + n], W_edge[(k + 1) * HC + n], lo);
    g_Bhi[n * 68 + kp] = hi;
    g_Blo[n * 68 + kp] = lo;
}

// ---------------- K1: node GEMMs (known-good) --------------------------------
__global__ void node_kernel(const float* __restrict__ x,
                            const float* __restrict__ W_msg,
                            const float* __restrict__ b_msg,
                            const float* __restrict__ W_self,
                            const float* __restrict__ b_self) {
    float* smf = (float*)dynsm;
    float* Xs = smf;
    float* Wm = smf + 64 * 128;
    float* Wf = Wm + 128 * 128;
    int tid = threadIdx.x;

    const float4* xg = (const float4*)(x + (size_t)blockIdx.x * 64 * DIN);
#pragma unroll
    for (int i = 0; i < 8; i++)  ((float4*)Xs)[tid + i * 256] = xg[tid + i * 256];
#pragma unroll
    for (int i = 0; i < 16; i++) ((float4*)Wm)[tid + i * 256] = ((const float4*)W_msg)[tid + i * 256];
#pragma unroll
    for (int i = 0; i < 8; i++)  ((float4*)Wf)[tid + i * 256] = ((const float4*)W_self)[tid + i * 256];
    __syncthreads();

    int lane = tid & 31, ty = tid >> 5;
    int lane4 = lane * 4;
    const float* Xr = Xs + ty * 8 * DIN;
    {
        float acc[8][4];
#pragma unroll
        for (int r = 0; r < 8; r++) { acc[r][0] = acc[r][1] = acc[r][2] = acc[r][3] = 0.f; }
#pragma unroll 4
        for (int k = 0; k < 128; k++) {
            float4 bq = *(float4*)(Wm + k * 128 + lane4);
#pragma unroll
            for (int r = 0; r < 8; r++) {
                float av = Xr[r * DIN + k];
                acc[r][0] += av * bq.x; acc[r][1] += av * bq.y;
                acc[r][2] += av * bq.z; acc[r][3] += av * bq.w;
            }
        }
        float4 bm = *(const float4*)(b_msg + lane4);
#pragma unroll
        for (int r = 0; r < 8; r++) {
            int n = blockIdx.x * 64 + ty * 8 + r;
            float4 v; v.x = acc[r][0] + bm.x; v.y = acc[r][1] + bm.y;
            v.z = acc[r][2] + bm.z; v.w = acc[r][3] + bm.w;
            *(float4*)(g_xm + (size_t)n * HC + lane4) = v;
        }
    }
    {
        int lane2 = lane * 2;
        float acc[8][2];
#pragma unroll
        for (int r = 0; r < 8; r++) { acc[r][0] = acc[r][1] = 0.f; }
#pragma unroll 4
        for (int k = 0; k < 128; k++) {
            float2 bq = *(float2*)(Wf + k * 64 + lane2);
#pragma unroll
            for (int r = 0; r < 8; r++) {
                float av = Xr[r * DIN + k];
                acc[r][0] += av * bq.x; acc[r][1] += av * bq.y;
            }
        }
        float2 bs = *(const float2*)(b_self + lane2);
#pragma unroll
        for (int r = 0; r < 8; r++) {
            int n = blockIdx.x * 64 + ty * 8 + r;
            float2 v; v.x = acc[r][0] + bs.x; v.y = acc[r][1] + bs.y;
            *(float2*)(g_xs + (size_t)n * OC + lane2) = v;
        }
    }
}

// ---------------- K2: warp-autonomous HMMA edge GEMM + fused scatter ---------
// Persistent CTAs, 3/SM (24 warps). Per tile of 64 edges:
//   - A fragments loaded from gmem and hi/lo split IN REGISTERS (no A smem)
//   - B hi/lo read from smem (loaded once per CTA)
//   - epilogue + attention + scatter straight from accumulator fragments
// NO __syncthreads in the tile loop: every warp runs free.
// warp w: rows [(w>>1)*16,+16), cols [(w&1)*64,+64)  (col half == head)
// smem: 0: bias[128] | 512: att[128] | 1024: B_hi(34816) | 35840: B_lo(34816)
#define SM_BHI   1024
#define SM_BLO   35840
#define SM_TOTAL 70656

__global__ void __launch_bounds__(256, 3) edge_kernel(
        const float* __restrict__ edge_attr,
        const float* __restrict__ b_edge,
        const float* __restrict__ att,
        const int*   __restrict__ srcIdx,
        const int*   __restrict__ dstIdx,
        float* __restrict__ le_out) {
    char* sm = dynsm;
    int tid = threadIdx.x;
    int wid = tid >> 5;
    int lane = tid & 31;
    float* b_s   = (float*)(sm);
    float* att_s = (float*)(sm + 512);
    uint32_t* Bh32 = (uint32_t*)(sm + SM_BHI);
    uint32_t* Bl32 = (uint32_t*)(sm + SM_BLO);

    // ---- prologue (once per CTA) ----
    if (tid < 128) { b_s[tid] = b_edge[tid]; att_s[tid] = att[tid]; }
    {
        const uint4* bh = (const uint4*)g_Bhi;
        const uint4* bl = (const uint4*)g_Blo;
        uint4* dh = (uint4*)Bh32;
        uint4* dl = (uint4*)Bl32;
#pragma unroll
        for (int i = 0; i < 9; i++) {
            int idx = tid + i * 256;
            if (idx < 2176) { dh[idx] = bh[idx]; dl[idx] = bl[idx]; }
        }
    }
    __syncthreads();   // the only block sync

    int rowg = wid >> 1;          // 0..3 -> rows rowg*16..+16
    int colg = wid & 1;           // 0..1 -> cols colg*64..+64  (== head)
    int r   = lane >> 2;          // 0..7
    int tig = lane & 3;           // 0..3
    int r0  = rowg * 16 + r;      // first row this lane covers
    // r1 = r0 + 8

    for (int t = blockIdx.x; t < NTILES; t += gridDim.x) {
        // A tile base, float2 (k-pair) units: row stride = 64 pairs
        const float2* A = (const float2*)(edge_attr + (size_t)t * 64 * DIN);

        // ---- MMA mainloop: A fragments from gmem, converted in regs ----
        float acc[8][4];
#pragma unroll
        for (int nf = 0; nf < 8; nf++)
#pragma unroll
            for (int q = 0; q < 4; q++) acc[nf][q] = 0.f;

        float2 raw0, raw1, raw2, raw3;
        {
            int kw = tig;   // ks = 0
            raw0 = A[r0 * 64 + kw];        raw1 = A[(r0 + 8) * 64 + kw];
            raw2 = A[r0 * 64 + kw + 4];    raw3 = A[(r0 + 8) * 64 + kw + 4];
        }
#pragma unroll
        for (int ks = 0; ks < 8; ks++) {
            int kw = ks * 8 + tig;
            uint32_t ah[4], al[4];
            ah[0] = pack_bf16x2_split(raw0.x, raw0.y, al[0]);
            ah[1] = pack_bf16x2_split(raw1.x, raw1.y, al[1]);
            ah[2] = pack_bf16x2_split(raw2.x, raw2.y, al[2]);
            ah[3] = pack_bf16x2_split(raw3.x, raw3.y, al[3]);
            if (ks < 7) {
                int kn = kw + 8;
                raw0 = A[r0 * 64 + kn];        raw1 = A[(r0 + 8) * 64 + kn];
                raw2 = A[r0 * 64 + kn + 4];    raw3 = A[(r0 + 8) * 64 + kn + 4];
            }
#pragma unroll
            for (int nf = 0; nf < 8; nf++) {
                int nb = (colg * 64 + nf * 8 + r) * 68 + kw;
                uint32_t bh[2] = { Bh32[nb], Bh32[nb + 4] };
                uint32_t bl[2] = { Bl32[nb], Bl32[nb + 4] };
                mma_bf16(acc[nf], ah, bh);
                mma_bf16(acc[nf], ah, bl);
                mma_bf16(acc[nf], al, bh);
            }
        }

        // ---- epilogue straight from fragments ----
        int e0 = t * 64 + r0;
        int e1 = e0 + 8;
        int s0 = srcIdx[e0], s1 = srcIdx[e1];
        int d0 = dstIdx[e0], d1 = dstIdx[e1];

        float dot0 = 0.f, dot1 = 0.f;
#pragma unroll
        for (int nf = 0; nf < 8; nf++) {
            int col = colg * 64 + nf * 8 + tig * 2;
            float2 bb = *(float2*)(b_s + col);
            // le = acc + bias ; store to gmem (4 lanes -> one 32B sector)
            float2 le0; le0.x = acc[nf][0] + bb.x; le0.y = acc[nf][1] + bb.y;
            float2 le1; le1.x = acc[nf][2] + bb.x; le1.y = acc[nf][3] + bb.y;
            *(float2*)(le_out + (size_t)e0 * HC + col) = le0;
            *(float2*)(le_out + (size_t)e1 * HC + col) = le1;
            // m = le + xm[src]  (reuse acc in place)
            float2 xv0 = *(const float2*)(g_xm + (size_t)s0 * HC + col);
            float2 xv1 = *(const float2*)(g_xm + (size_t)s1 * HC + col);
            acc[nf][0] = le0.x + xv0.x; acc[nf][1] = le0.y + xv0.y;
            acc[nf][2] = le1.x + xv1.x; acc[nf][3] = le1.y + xv1.y;
            float2 at = *(float2*)(att_s + col);
            dot0 += acc[nf][0] * at.x + acc[nf][1] * at.y;
            dot1 += acc[nf][2] * at.x + acc[nf][3] * at.y;
        }
        // reduce over the 4 tig lanes (same row, same head)
        dot0 += __shfl_xor_sync(0xffffffffu, dot0, 1);
        dot0 += __shfl_xor_sync(0xffffffffu, dot0, 2);
        dot1 += __shfl_xor_sync(0xffffffffu, dot1, 1);
        dot1 += __shfl_xor_sync(0xffffffffu, dot1, 2);
        float lr0 = dot0 > 0.f ? dot0 : 0.2f * dot0;
        float lr1 = dot1 > 0.f ? dot1 : 0.2f * dot1;
        float ex0 = __expf(lr0);
        float ex1 = __expf(lr1);
        if (tig == 0) {
            red_add_f32(&g_denom[d0 * 2 + colg], ex0);
            red_add_f32(&g_denom[d1 * 2 + colg], ex1);
        }
#pragma unroll
        for (int nf = 0; nf < 8; nf++) {
            int col = colg * 64 + nf * 8 + tig * 2;
            red_add_v2(g_agg + (size_t)d0 * HC + col, acc[nf][0] * ex0, acc[nf][1] * ex0);
            red_add_v2(g_agg + (size_t)d1 * HC + col, acc[nf][2] * ex1, acc[nf][3] * ex1);
        }
    }
}

// ---------------- K3: finalize ----------------------------------------------
__global__ void finalize_kernel(float* __restrict__ out) {
    int i = blockIdx.x * blockDim.x + threadIdx.x;
    if (i >= NODES * OC) return;
    int n = i >> 6;
    int c = i & 63;
    float d0 = g_denom[n * 2 + 0] + 1e-16f;
    float d1 = g_denom[n * 2 + 1] + 1e-16f;
    float v = 0.5f * (g_agg[(size_t)n * HC + c] / d0 + g_agg[(size_t)n * HC + 64 + c] / d1);
    out[i] = v + g_xs[i];
}

// ---------------- launch ------------------------------------------------------
extern "C" void kernel_launch(void* const* d_in, const int* in_sizes, int n_in,
                              void* d_out, int out_size) {
    const float* x        = (const float*)d_in[0];
    const float* edge_attr= (const float*)d_in[1];
    const float* W_msg    = (const float*)d_in[2];
    const float* b_msg    = (const float*)d_in[3];
    const float* W_edge   = (const float*)d_in[4];
    const float* b_edge   = (const float*)d_in[5];
    const float* W_self   = (const float*)d_in[6];
    const float* b_self   = (const float*)d_in[7];
    const float* att      = (const float*)d_in[8];
    const int*   ei       = (const int*)d_in[9];
    const int* srcI = ei;
    const int* dstI = ei + EDGES;

    float* out = (float*)d_out;
    float* le_out;
    bool le_in_out = (out_size >= NODES * OC + (long long)EDGES * HC);
    if (le_in_out) {
        le_out = out + (size_t)NODES * OC;
    } else {
        void* p = nullptr;
        cudaGetSymbolAddress(&p, g_le_fallback);
        le_out = (float*)p;
    }

    cudaFuncSetAttribute(node_kernel, cudaFuncAttributeMaxDynamicSharedMemorySize, 131072);
    cudaFuncSetAttribute(edge_kernel, cudaFuncAttributeMaxDynamicSharedMemorySize, SM_TOTAL);

    init_kernel<<<(NODES * HC + 255) / 256, 256>>>();
    prep_kernel<<<32, 256>>>(W_edge);
    node_kernel<<<NODES / 64, 256, 131072>>>(x, W_msg, b_msg, W_self, b_self);
    edge_kernel<<<444, 256, SM_TOTAL>>>(edge_attr, b_edge, att, srcI, dstI, le_out);
    finalize_kernel<<<(NODES * OC + 255) / 256, 256>>>(out);
}

// round 10
// speedup vs baseline: 1.5562x; 1.1120x over previous
#include <cuda_runtime.h>
#include <cuda_bf16.h>
#include <cstdint>

#define NODES 40000
#define EDGES 640000
#define DIN   128
#define HC    128
#define OC    64
#define NTILES 5000   // 128 edges per tile

typedef unsigned long long ull;

// single dynamic-shared declaration for the whole TU
extern __shared__ char dynsm[];

// ---------------- device scratch ------------------------------------------
__device__ float g_xm[(size_t)NODES * HC];
__device__ float g_xs[(size_t)NODES * OC];
__device__ float g_denom[(size_t)NODES * 2];
__device__ float g_agg[(size_t)NODES * HC];
__device__ float g_le_fallback[(size_t)EDGES * HC];
// W_edge^T split into bf16 hi/lo: [n][k-pair] padded row stride 68 words
__device__ __align__(16) uint32_t g_Bhi[128 * 68];
__device__ __align__(16) uint32_t g_Blo[128 * 68];

// ---------------- helpers ----------------------------------------------------
__device__ __forceinline__ void red_add_v2(float* p, float a, float b) {
    asm volatile("red.global.add.v2.f32 [%0], {%1,%2};"
                 :: "l"(p), "f"(a), "f"(b) : "memory");
}
__device__ __forceinline__ void red_add_f32(float* p, float v) {
    asm volatile("red.global.add.f32 [%0], %1;" :: "l"(p), "f"(v) : "memory");
}
// m16n8k16 row.col bf16 MMA, f32 accumulate (base-target HMMA)
__device__ __forceinline__ void mma_bf16(float* c, const uint32_t* a, const uint32_t* b) {
    asm volatile("mma.sync.aligned.m16n8k16.row.col.f32.bf16.bf16.f32 "
                 "{%0,%1,%2,%3}, {%4,%5,%6,%7}, {%8,%9}, {%0,%1,%2,%3};"
                 : "+f"(c[0]), "+f"(c[1]), "+f"(c[2]), "+f"(c[3])
                 : "r"(a[0]), "r"(a[1]), "r"(a[2]), "r"(a[3]), "r"(b[0]), "r"(b[1]));
}
__device__ __forceinline__ uint32_t pack_bf16x2_split(float v0, float v1, uint32_t& lo) {
    __nv_bfloat16 h0 = __float2bfloat16_rn(v0);
    __nv_bfloat16 h1 = __float2bfloat16_rn(v1);
    __nv_bfloat16 l0 = __float2bfloat16_rn(v0 - __bfloat162float(h0));
    __nv_bfloat16 l1 = __float2bfloat16_rn(v1 - __bfloat162float(h1));
    lo = (uint32_t)__bfloat16_as_ushort(l0) | ((uint32_t)__bfloat16_as_ushort(l1) << 16);
    return (uint32_t)__bfloat16_as_ushort(h0) | ((uint32_t)__bfloat16_as_ushort(h1) << 16);
}

// ---------------- K0: init --------------------------------------------------
__global__ void init_kernel() {
    int i = blockIdx.x * blockDim.x + threadIdx.x;
    if (i < NODES * HC) g_agg[i] = 0.0f;
    if (i < NODES * 2)  g_denom[i] = 0.0f;
}

// ---------------- prep: W_edge^T -> bf16 hi/lo padded [n][k] images ----------
__global__ void prep_kernel(const float* __restrict__ W_edge) {
    int p = blockIdx.x * 256 + threadIdx.x;   // 8192 = 128 n x 64 k-pairs
    if (p >= 8192) return;
    int n  = p >> 6;
    int kp = p & 63;
    int k  = kp * 2;
    uint32_t lo;
    uint32_t hi = pack_bf16x2_split(W_edge[k * HC + n], W_edge[(k + 1) * HC + n], lo);
    g_Bhi[n * 68 + kp] = hi;
    g_Blo[n * 68 + kp] = lo;
}

// ---------------- K1: node GEMMs (known-good) --------------------------------
__global__ void node_kernel(const float* __restrict__ x,
                            const float* __restrict__ W_msg,
                            const float* __restrict__ b_msg,
                            const float* __restrict__ W_self,
                            const float* __restrict__ b_self) {
    float* smf = (float*)dynsm;
    float* Xs = smf;
    float* Wm = smf + 64 * 128;
    float* Wf = Wm + 128 * 128;
    int tid = threadIdx.x;

    const float4* xg = (const float4*)(x + (size_t)blockIdx.x * 64 * DIN);
#pragma unroll
    for (int i = 0; i < 8; i++)  ((float4*)Xs)[tid + i * 256] = xg[tid + i * 256];
#pragma unroll
    for (int i = 0; i < 16; i++) ((float4*)Wm)[tid + i * 256] = ((const float4*)W_msg)[tid + i * 256];
#pragma unroll
    for (int i = 0; i < 8; i++)  ((float4*)Wf)[tid + i * 256] = ((const float4*)W_self)[tid + i * 256];
    __syncthreads();

    int lane = tid & 31, ty = tid >> 5;
    int lane4 = lane * 4;
    const float* Xr = Xs + ty * 8 * DIN;
    {
        float acc[8][4];
#pragma unroll
        for (int r = 0; r < 8; r++) { acc[r][0] = acc[r][1] = acc[r][2] = acc[r][3] = 0.f; }
#pragma unroll 4
        for (int k = 0; k < 128; k++) {
            float4 bq = *(float4*)(Wm + k * 128 + lane4);
#pragma unroll
            for (int r = 0; r < 8; r++) {
                float av = Xr[r * DIN + k];
                acc[r][0] += av * bq.x; acc[r][1] += av * bq.y;
                acc[r][2] += av * bq.z; acc[r][3] += av * bq.w;
            }
        }
        float4 bm = *(const float4*)(b_msg + lane4);
#pragma unroll
        for (int r = 0; r < 8; r++) {
            int n = blockIdx.x * 64 + ty * 8 + r;
            float4 v; v.x = acc[r][0] + bm.x; v.y = acc[r][1] + bm.y;
            v.z = acc[r][2] + bm.z; v.w = acc[r][3] + bm.w;
            *(float4*)(g_xm + (size_t)n * HC + lane4) = v;
        }
    }
    {
        int lane2 = lane * 2;
        float acc[8][2];
#pragma unroll
        for (int r = 0; r < 8; r++) { acc[r][0] = acc[r][1] = 0.f; }
#pragma unroll 4
        for (int k = 0; k < 128; k++) {
            float2 bq = *(float2*)(Wf + k * 64 + lane2);
#pragma unroll
            for (int r = 0; r < 8; r++) {
                float av = Xr[r * DIN + k];
                acc[r][0] += av * bq.x; acc[r][1] += av * bq.y;
            }
        }
        float2 bs = *(const float2*)(b_self + lane2);
#pragma unroll
        for (int r = 0; r < 8; r++) {
            int n = blockIdx.x * 64 + ty * 8 + r;
            float2 v; v.x = acc[r][0] + bs.x; v.y = acc[r][1] + bs.y;
            *(float2*)(g_xs + (size_t)n * OC + lane2) = v;
        }
    }
}

// ---------------- K2: warp-autonomous HMMA edge GEMM + fused scatter ---------
// Persistent CTAs, 2/SM. Tile = 128 edges; each warp computes 32 rows x 64
// cols as TWO stacked m16 tiles sharing the same B fragments -> B smem bytes
// per edge HALVED vs R9 (L1 wavefront pipe was the binding constraint).
// A fragments loaded from gmem and hi/lo split in registers; epilogue and
// scatter straight from fragments. No __syncthreads in the tile loop.
// warp w: rows [(w>>1)*32,+32), cols [(w&1)*64,+64)  (col half == head)
// smem: 0: bias[128] | 512: att[128] | 1024: B_hi(34816) | 35840: B_lo(34816)
#define SM_BHI   1024
#define SM_BLO   35840
#define SM_TOTAL 70656

__global__ void __launch_bounds__(256, 2) edge_kernel(
        const float* __restrict__ edge_attr,
        const float* __restrict__ b_edge,
        const float* __restrict__ att,
        const int*   __restrict__ srcIdx,
        const int*   __restrict__ dstIdx,
        float* __restrict__ le_out) {
    char* sm = dynsm;
    int tid = threadIdx.x;
    int wid = tid >> 5;
    int lane = tid & 31;
    float* b_s   = (float*)(sm);
    float* att_s = (float*)(sm + 512);
    uint32_t* Bh32 = (uint32_t*)(sm + SM_BHI);
    uint32_t* Bl32 = (uint32_t*)(sm + SM_BLO);

    // ---- prologue (once per CTA) ----
    if (tid < 128) { b_s[tid] = b_edge[tid]; att_s[tid] = att[tid]; }
    {
        const uint4* bh = (const uint4*)g_Bhi;
        const uint4* bl = (const uint4*)g_Blo;
        uint4* dh = (uint4*)Bh32;
        uint4* dl = (uint4*)Bl32;
#pragma unroll
        for (int i = 0; i < 9; i++) {
            int idx = tid + i * 256;
            if (idx < 2176) { dh[idx] = bh[idx]; dl[idx] = bl[idx]; }
        }
    }
    __syncthreads();   // the only block sync

    int rowg = wid >> 1;          // 0..3 -> rows rowg*32..+32
    int colg = wid & 1;           // 0..1 -> cols colg*64..+64  (== head)
    int r   = lane >> 2;          // 0..7
    int tig = lane & 3;           // 0..3
    int r0  = rowg * 32 + r;      // lane covers rows r0, r0+8 (mt=0), r0+16, r0+24 (mt=1)

    for (int t = blockIdx.x; t < NTILES; t += gridDim.x) {
        // A tile base, float2 (k-pair) units: row stride = 64 pairs
        const float2* A = (const float2*)(edge_attr + (size_t)t * 128 * DIN);

        float acc[2][8][4];
#pragma unroll
        for (int mt = 0; mt < 2; mt++)
#pragma unroll
            for (int nf = 0; nf < 8; nf++)
#pragma unroll
                for (int q = 0; q < 4; q++) acc[mt][nf][q] = 0.f;

        // prefetch first ks raw A: 8 float2 (2 m-tiles x rows r,r+8 x kw,kw+4)
        float2 raw[2][4];
        {
            int kw = tig;
#pragma unroll
            for (int mt = 0; mt < 2; mt++) {
                int R = r0 + mt * 16;
                raw[mt][0] = A[R * 64 + kw];       raw[mt][1] = A[(R + 8) * 64 + kw];
                raw[mt][2] = A[R * 64 + kw + 4];   raw[mt][3] = A[(R + 8) * 64 + kw + 4];
            }
        }
#pragma unroll
        for (int ks = 0; ks < 8; ks++) {
            int kw = ks * 8 + tig;
            uint32_t ah[2][4], al[2][4];
#pragma unroll
            for (int mt = 0; mt < 2; mt++) {
                ah[mt][0] = pack_bf16x2_split(raw[mt][0].x, raw[mt][0].y, al[mt][0]);
                ah[mt][1] = pack_bf16x2_split(raw[mt][1].x, raw[mt][1].y, al[mt][1]);
                ah[mt][2] = pack_bf16x2_split(raw[mt][2].x, raw[mt][2].y, al[mt][2]);
                ah[mt][3] = pack_bf16x2_split(raw[mt][3].x, raw[mt][3].y, al[mt][3]);
            }
            if (ks < 7) {
                int kn = kw + 8;
#pragma unroll
                for (int mt = 0; mt < 2; mt++) {
                    int R = r0 + mt * 16;
                    raw[mt][0] = A[R * 64 + kn];       raw[mt][1] = A[(R + 8) * 64 + kn];
                    raw[mt][2] = A[R * 64 + kn + 4];   raw[mt][3] = A[(R + 8) * 64 + kn + 4];
                }
            }
#pragma unroll
            for (int nf = 0; nf < 8; nf++) {
                int nb = (colg * 64 + nf * 8 + r) * 68 + kw;
                uint32_t bh[2] = { Bh32[nb], Bh32[nb + 4] };
                uint32_t bl[2] = { Bl32[nb], Bl32[nb + 4] };
#pragma unroll
                for (int mt = 0; mt < 2; mt++) {
                    mma_bf16(acc[mt][nf], ah[mt], bh);
                    mma_bf16(acc[mt][nf], ah[mt], bl);
                    mma_bf16(acc[mt][nf], al[mt], bh);
                }
            }
        }

        // ---- epilogue straight from fragments (per m-tile) ----
#pragma unroll
        for (int mt = 0; mt < 2; mt++) {
            int e0 = t * 128 + r0 + mt * 16;
            int e1 = e0 + 8;
            int s0 = srcIdx[e0], s1 = srcIdx[e1];
            int d0 = dstIdx[e0], d1 = dstIdx[e1];

            float dot0 = 0.f, dot1 = 0.f;
#pragma unroll
            for (int nf = 0; nf < 8; nf++) {
                int col = colg * 64 + nf * 8 + tig * 2;
                float2 bb = *(float2*)(b_s + col);
                float2 le0; le0.x = acc[mt][nf][0] + bb.x; le0.y = acc[mt][nf][1] + bb.y;
                float2 le1; le1.x = acc[mt][nf][2] + bb.x; le1.y = acc[mt][nf][3] + bb.y;
                *(float2*)(le_out + (size_t)e0 * HC + col) = le0;
                *(float2*)(le_out + (size_t)e1 * HC + col) = le1;
                float2 xv0 = *(const float2*)(g_xm + (size_t)s0 * HC + col);
                float2 xv1 = *(const float2*)(g_xm + (size_t)s1 * HC + col);
                acc[mt][nf][0] = le0.x + xv0.x; acc[mt][nf][1] = le0.y + xv0.y;
                acc[mt][nf][2] = le1.x + xv1.x; acc[mt][nf][3] = le1.y + xv1.y;
                float2 at = *(float2*)(att_s + col);
                dot0 += acc[mt][nf][0] * at.x + acc[mt][nf][1] * at.y;
                dot1 += acc[mt][nf][2] * at.x + acc[mt][nf][3] * at.y;
            }
            dot0 += __shfl_xor_sync(0xffffffffu, dot0, 1);
            dot0 += __shfl_xor_sync(0xffffffffu, dot0, 2);
            dot1 += __shfl_xor_sync(0xffffffffu, dot1, 1);
            dot1 += __shfl_xor_sync(0xffffffffu, dot1, 2);
            float lr0 = dot0 > 0.f ? dot0 : 0.2f * dot0;
            float lr1 = dot1 > 0.f ? dot1 : 0.2f * dot1;
            float ex0 = __expf(lr0);
            float ex1 = __expf(lr1);
            if (tig == 0) {
                red_add_f32(&g_denom[d0 * 2 + colg], ex0);
                red_add_f32(&g_denom[d1 * 2 + colg], ex1);
            }
#pragma unroll
            for (int nf = 0; nf < 8; nf++) {
                int col = colg * 64 + nf * 8 + tig * 2;
                red_add_v2(g_agg + (size_t)d0 * HC + col, acc[mt][nf][0] * ex0, acc[mt][nf][1] * ex0);
                red_add_v2(g_agg + (size_t)d1 * HC + col, acc[mt][nf][2] * ex1, acc[mt][nf][3] * ex1);
            }
        }
    }
}

// ---------------- K3: finalize ----------------------------------------------
__global__ void finalize_kernel(float* __restrict__ out) {
    int i = blockIdx.x * blockDim.x + threadIdx.x;
    if (i >= NODES * OC) return;
    int n = i >> 6;
    int c = i & 63;
    float d0 = g_denom[n * 2 + 0] + 1e-16f;
    float d1 = g_denom[n * 2 + 1] + 1e-16f;
    float v = 0.5f * (g_agg[(size_t)n * HC + c] / d0 + g_agg[(size_t)n * HC + 64 + c] / d1);
    out[i] = v + g_xs[i];
}

// ---------------- launch ------------------------------------------------------
extern "C" void kernel_launch(void* const* d_in, const int* in_sizes, int n_in,
                              void* d_out, int out_size) {
    const float* x        = (const float*)d_in[0];
    const float* edge_attr= (const float*)d_in[1];
    const float* W_msg    = (const float*)d_in[2];
    const float* b_msg    = (const float*)d_in[3];
    const float* W_edge   = (const float*)d_in[4];
    const float* b_edge   = (const float*)d_in[5];
    const float* W_self   = (const float*)d_in[6];
    const float* b_self   = (const float*)d_in[7];
    const float* att      = (const float*)d_in[8];
    const int*   ei       = (const int*)d_in[9];
    const int* srcI = ei;
    const int* dstI = ei + EDGES;

    float* out = (float*)d_out;
    float* le_out;
    bool le_in_out = (out_size >= NODES * OC + (long long)EDGES * HC);
    if (le_in_out) {
        le_out = out + (size_t)NODES * OC;
    } else {
        void* p = nullptr;
        cudaGetSymbolAddress(&p, g_le_fallback);
        le_out = (float*)p;
    }

    cudaFuncSetAttribute(node_kernel, cudaFuncAttributeMaxDynamicSharedMemorySize, 131072);
    cudaFuncSetAttribute(edge_kernel, cudaFuncAttributeMaxDynamicSharedMemorySize, SM_TOTAL);

    init_kernel<<<(NODES * HC + 255) / 256, 256>>>();
    prep_kernel<<<32, 256>>>(W_edge);
    node_kernel<<<NODES / 64, 256, 131072>>>(x, W_msg, b_msg, W_self, b_self);
    edge_kernel<<<296, 256, SM_TOTAL>>>(edge_attr, b_edge, att, srcI, dstI, le_out);
    finalize_kernel<<<(NODES * OC + 255) / 256, 256>>>(out);
}